// round 16
// baseline (speedup 1.0000x reference)
#include <cuda_runtime.h>
#include <math.h>

// Problem constants (B=1, C_IN=3, H=W=96, FEAT=64, GDIM=8, BLOCK=16)
#define Hh   96
#define Ww   96
#define HW   (96 * 96)
#define GD   8
#define FEAT 64
#define CIN  3

#define NB   144   // blocks: <=148 SMs, 1 block/SM -> all co-resident in wave 1
#define NT   512   // threads/block: 64 gaussians x 8 channel-lanes

#define LN255 5.5412635f   // ln(255); alpha >= 1/255  <=>  sigma <= ln(255)

// 32-byte gaussian record (tile bounds proven redundant: radius >= 2 always,
// and any sigma-gate survivor has |d| <= 1.665 < radius => tile test passes).
struct __align__(16) GParam {
    float cx, cy, ca, cb, cc, r0, r1, r2;
};

__device__ GParam g_gauss[HW];   // 288 KB scratch (device global: no allocations)
__device__ int    g_arrive = 0;  // grid barrier counters (self-resetting per launch)
__device__ int    g_depart = 0;

// ---------------------------------------------------------------------------
// Fused kernel, compressed critical path:
//   prefetch conv inputs to REGISTERS -> stage weights -> collapse -> conv
//   (reg-fed) -> A2 split across the 8 lanes of each gaussian via shfl (no
//   block barrier) -> grid barrier -> raster (exact 5x5) -> reset.
// Barrier, raster and reset are byte-identical to the 12.8us R12 kernel.
// ---------------------------------------------------------------------------
__global__ __launch_bounds__(NT)
void fused_kernel(const float* __restrict__ inp,
                  const float* __restrict__ w_enc,
                  const float* __restrict__ b_enc,
                  const float* __restrict__ w_head,
                  const float* __restrict__ b_head,
                  float* __restrict__ out)
{
    __shared__ float s_we[FEAT * 27];   // w_enc  [c*27 + k]
    __shared__ float s_wh[FEAT * GD];   // w_head TRANSPOSED [c*8 + o]
    __shared__ float s_be[FEAT];
    __shared__ float s_bh[GD];
    __shared__ float sw[GD * 27];       // collapsed weights [o*27 + k]
    __shared__ float sb[GD];

    const int tid = threadIdx.x;
    const int bid = blockIdx.x;
    const int p0  = bid * 64;

    const int gi  = tid >> 3;           // gaussian within block [0,64)
    const int o   = tid & 7;            // channel lane
    const int p   = p0 + gi;
    const int wpx = p % Ww;
    const int hpx = p / Ww;

    // ---- prefetch conv inputs into registers (issued before anything else) -
    float v[27];
    #pragma unroll
    for (int ci = 0; ci < CIN; ++ci) {
        #pragma unroll
        for (int ky = 0; ky < 3; ++ky) {
            const int y = hpx + ky - 1;
            #pragma unroll
            for (int kx = 0; kx < 3; ++kx) {
                const int x = wpx + kx - 1;
                float t = 0.f;
                if ((unsigned)y < Hh && (unsigned)x < Ww)
                    t = __ldg(&inp[ci * HW + y * Ww + x]);
                v[ci * 9 + ky * 3 + kx] = t;
            }
        }
    }

    // ---- stage raw weights to shared ---------------------------------------
    for (int t = tid; t < FEAT * 27; t += NT) s_we[t] = __ldg(&w_enc[t]);
    {   // transpose w_head into [c][o]  (tid < 512 == FEAT*GD)
        const int c = tid >> 3, oo = tid & 7;
        s_wh[c * GD + oo] = __ldg(&w_head[oo * FEAT + c]);
    }
    if (tid < FEAT) s_be[tid] = __ldg(&b_enc[tid]);
    if (tid < GD)   s_bh[tid] = __ldg(&b_head[tid]);
    __syncthreads();

    // ---- collapse: w_eff[o,k] = sum_c w_head[o,c] * w_enc[c,k] -------------
    if (tid < GD * 27) {
        const int oo = tid / 27, k = tid % 27;
        float a0 = 0.f, a1 = 0.f, a2 = 0.f, a3 = 0.f;
        #pragma unroll
        for (int c = 0; c < FEAT; c += 4) {
            a0 += s_wh[(c    ) * GD + oo] * s_we[(c    ) * 27 + k];
            a1 += s_wh[(c + 1) * GD + oo] * s_we[(c + 1) * 27 + k];
            a2 += s_wh[(c + 2) * GD + oo] * s_we[(c + 2) * 27 + k];
            a3 += s_wh[(c + 3) * GD + oo] * s_we[(c + 3) * 27 + k];
        }
        sw[tid] = (a0 + a1) + (a2 + a3);
    } else if (tid < GD * 27 + GD) {
        const int oo = tid - GD * 27;
        float acc = s_bh[oo];
        #pragma unroll
        for (int c = 0; c < FEAT; ++c)
            acc += s_wh[c * GD + oo] * s_be[c];
        sb[oo] = acc;
    }
    __syncthreads();

    // ---- conv: 27 register-fed FMAs per (gaussian, channel) thread ---------
    float acc = sb[o];
    #pragma unroll
    for (int k = 0; k < 27; ++k)
        acc += v[k] * sw[o * 27 + k];

    // ---- A2 split across the 8 lanes of each gaussian (warp-local) ---------
    // lane 3: theta chain -> cos,sin ; lanes 4/5: scale^2 ; lanes 6/7: tanh.
    float t_c = 0.f, t_s = 0.f, t_sq = 0.f, t_off = 0.f;
    if (o == 3) {
        const float theta = (1.f / (1.f + __expf(-acc))) * 6.283185307179586f;
        t_c = __cosf(theta);
        t_s = __sinf(theta);
    } else if (o == 4 || o == 5) {
        const float sc = (1.f / (1.f + __expf(-acc))) * 0.5f + 1e-6f;
        t_sq = sc * sc;
    } else if (o >= 6) {
        t_off = tanhf(acc);
    }

    // gather to lane 0 of each 8-lane group (full-warp shfl, aligned groups)
    const int base = tid & 31 & ~7;     // group base lane within warp
    const float r1f  = __shfl_sync(0xFFFFFFFFu, acc,   base + 1);
    const float r2f  = __shfl_sync(0xFFFFFFFFu, acc,   base + 2);
    const float cth  = __shfl_sync(0xFFFFFFFFu, t_c,   base + 3);
    const float sth  = __shfl_sync(0xFFFFFFFFu, t_s,   base + 3);
    const float v0   = __shfl_sync(0xFFFFFFFFu, t_sq,  base + 4);
    const float v1   = __shfl_sync(0xFFFFFFFFu, t_sq,  base + 5);
    const float off0 = __shfl_sync(0xFFFFFFFFu, t_off, base + 6);
    const float off1 = __shfl_sync(0xFFFFFFFFu, t_off, base + 7);

    if (o == 0) {
        const float S00 = cth * cth * v0 + sth * sth * v1;
        const float S01 = cth * sth * (v0 - v1);
        const float S11 = sth * sth * v0 + cth * cth * v1;
        const float det = S00 * S11 - S01 * S01;
        const float inv_det = 1.f / det;

        const float coord0 = 2.0f * (float)wpx / (float)Ww - 1.0f;
        const float coord1 = 2.0f * (float)hpx / (float)Hh - 1.0f;
        const float x_ndc = coord0 + 2.0f * off0 / (float)Ww - 1.0f / (float)Ww;
        const float y_ndc = coord1 + 2.0f * off1 / (float)Hh - 1.0f / (float)Hh;

        float4 q0, q1;
        q0.x = 0.5f * (float)Ww * (x_ndc + 1.0f) - 0.5f;   // cx
        q0.y = 0.5f * (float)Hh * (y_ndc + 1.0f) - 0.5f;   // cy
        q0.z =  S11 * inv_det;                             // ca
        q0.w = -S01 * inv_det;                             // cb
        q1.x =  S00 * inv_det;                             // cc
        q1.y = acc;                                        // r0 (own lane)
        q1.z = r1f;                                        // r1
        q1.w = r2f;                                        // r2
        float4* dst = reinterpret_cast<float4*>(&g_gauss[p]);
        dst[0] = q0;
        dst[1] = q1;
    }

    // ---- device-wide barrier (unchanged from 12.8us kernel) ----------------
    __threadfence();                     // publish g_gauss GPU-wide
    __syncthreads();                     // whole block done writing
    if (tid == 0) {
        atomicAdd(&g_arrive, 1);
        while (*(volatile int*)&g_arrive < NB) { }
        __threadfence();
        atomicAdd(&g_depart, 1);         // "I will never read g_arrive again"
    }
    __syncthreads();                     // released; all g_gauss visible

    // ---- phase B: rasterize, 8 lanes per pixel, exact 5x5 window -----------
    {
        const int px = wpx;
        const int py = hpx;
        const float fpx = (float)px;
        const float fpy = (float)py;

        float a0 = 0.f, a1 = 0.f, a2 = 0.f;

        #pragma unroll
        for (int j = o; j < 25; j += 8) {
            const int gh = py - 1 + j / 5;
            const int gw = px - 1 + j % 5;
            if ((unsigned)gh >= Hh || (unsigned)gw >= Ww) continue;
            const float4* q = reinterpret_cast<const float4*>(&g_gauss[gh * Ww + gw]);
            const float4 q0 = q[0];      // cx, cy, ca, cb
            const float4 q1 = q[1];      // cc, r0, r1, r2
            const float dx = q0.x - fpx;
            const float dy = q0.y - fpy;
            const float sigma = 0.5f * (q0.z * dx * dx + q1.x * dy * dy) + q0.w * dx * dy;
            if (!(sigma >= 0.f) || sigma > LN255) continue;
            const float alpha = fminf(0.999f, __expf(-sigma));
            a0 += alpha * q1.y;
            a1 += alpha * q1.z;
            a2 += alpha * q1.w;
        }

        #pragma unroll
        for (int m = 1; m < 8; m <<= 1) {
            a0 += __shfl_xor_sync(0xFFFFFFFFu, a0, m);
            a1 += __shfl_xor_sync(0xFFFFFFFFu, a1, m);
            a2 += __shfl_xor_sync(0xFFFFFFFFu, a2, m);
        }

        if (o == 0)      out[0 * HW + p] = fminf(fmaxf(a0, 0.f), 1.f);
        else if (o == 1) out[1 * HW + p] = fminf(fmaxf(a1, 0.f), 1.f);
        else if (o == 2) out[2 * HW + p] = fminf(fmaxf(a2, 0.f), 1.f);
    }

    // ---- reset barrier counters for the next graph replay ------------------
    if (bid == 0 && tid == 0) {
        while (*(volatile int*)&g_depart < NB) { }   // nobody touches g_arrive anymore
        atomicExch(&g_arrive, 0);
        atomicExch(&g_depart, 0);
    }
}

// ---------------------------------------------------------------------------
extern "C" void kernel_launch(void* const* d_in, const int* in_sizes, int n_in,
                              void* d_out, int out_size)
{
    const float* inp    = (const float*)d_in[0];
    const float* w_enc  = (const float*)d_in[1];
    const float* b_enc  = (const float*)d_in[2];
    const float* w_head = (const float*)d_in[3];
    const float* b_head = (const float*)d_in[4];
    float* out = (float*)d_out;

    fused_kernel<<<NB, NT>>>(inp, w_enc, b_enc, w_head, b_head, out);
}

// round 17
// speedup vs baseline: 1.2553x; 1.2553x over previous
#include <cuda_runtime.h>
#include <math.h>

// Problem constants (B=1, C_IN=3, H=W=96, FEAT=64, GDIM=8, BLOCK=16)
#define Hh   96
#define Ww   96
#define HW   (96 * 96)
#define GD   8
#define FEAT 64
#define CIN  3

#define NB   144   // blocks: <=148 SMs, 1 block/SM -> all co-resident in wave 1
#define NT   512   // threads/block: 64 gaussians x 8 outputs; 64 pixels x 8 lanes

#define LN255 5.5412635f   // ln(255); alpha >= 1/255  <=>  sigma <= ln(255)

// 32-byte gaussian record (tile bounds proven redundant: radius >= 2 always,
// and any sigma-gate survivor has |d| <= 1.665 < radius => tile test passes).
struct __align__(16) GParam {
    float cx, cy, ca, cb, cc, r0, r1, r2;
};

__device__ GParam g_gauss[HW];   // 288 KB scratch (device global: no allocations)
__device__ int    g_arrive = 0;  // MONOTONIC epoch barrier counter (never reset)

// ---------------------------------------------------------------------------
// Single fused kernel (R12 structure): stage weights -> collapse conv+head ->
// conv -> activations -> EPOCH grid barrier -> rasterize over the exact 5x5
// window. Only the barrier protocol differs from the 12.8us kernel:
// one atomic per block, no depart counter, no reset. Replays are serialized
// by the graph, so replay k's arrivals occupy counts [k*NB, (k+1)*NB) and
// every block waits for (k+1)*NB.
// ---------------------------------------------------------------------------
__global__ __launch_bounds__(NT)
void fused_kernel(const float* __restrict__ inp,
                  const float* __restrict__ w_enc,
                  const float* __restrict__ b_enc,
                  const float* __restrict__ w_head,
                  const float* __restrict__ b_head,
                  float* __restrict__ out)
{
    __shared__ float s_we[FEAT * 27];   // w_enc  [c*27 + k]
    __shared__ float s_wh[FEAT * GD];   // w_head TRANSPOSED [c*8 + o]
    __shared__ float s_be[FEAT];
    __shared__ float s_bh[GD];
    __shared__ float sw[GD * 27];       // collapsed weights [o*27 + k]
    __shared__ float sb[GD];
    __shared__ float spred[64 * GD];    // per-gaussian raw preds [gi*8 + o]

    const int tid = threadIdx.x;
    const int bid = blockIdx.x;

    // ---- stage raw weights to shared (one coalesced cold-DRAM trip) --------
    for (int t = tid; t < FEAT * 27; t += NT) s_we[t] = __ldg(&w_enc[t]);
    {   // transpose w_head into [c][o]
        const int c = tid >> 3, o = tid & 7;           // tid < 512 == FEAT*GD
        s_wh[c * GD + o] = __ldg(&w_head[o * FEAT + c]);
    }
    if (tid < FEAT) s_be[tid] = __ldg(&b_enc[tid]);
    if (tid < GD)   s_bh[tid] = __ldg(&b_head[tid]);
    __syncthreads();

    // ---- collapse: w_eff[o,k] = sum_c w_head[o,c] * w_enc[c,k] -------------
    if (tid < GD * 27) {
        const int o = tid / 27, k = tid % 27;
        float a0 = 0.f, a1 = 0.f, a2 = 0.f, a3 = 0.f;
        #pragma unroll
        for (int c = 0; c < FEAT; c += 4) {
            a0 += s_wh[(c    ) * GD + o] * s_we[(c    ) * 27 + k];
            a1 += s_wh[(c + 1) * GD + o] * s_we[(c + 1) * 27 + k];
            a2 += s_wh[(c + 2) * GD + o] * s_we[(c + 2) * 27 + k];
            a3 += s_wh[(c + 3) * GD + o] * s_we[(c + 3) * 27 + k];
        }
        sw[tid] = (a0 + a1) + (a2 + a3);
    } else if (tid < GD * 27 + GD) {
        const int o = tid - GD * 27;
        float acc = s_bh[o];
        #pragma unroll
        for (int c = 0; c < FEAT; ++c)
            acc += s_wh[c * GD + o] * s_be[c];
        sb[o] = acc;
    }
    __syncthreads();

    // ---- phase A1: conv, 8 threads per gaussian (27 MACs each) -------------
    {
        const int gi = tid >> 3;          // gaussian within block [0,64)
        const int o  = tid & 7;           // output channel
        const int p  = bid * 64 + gi;     // [0, HW)
        const int w  = p % Ww;
        const int h  = p / Ww;

        float acc = sb[o];
        #pragma unroll
        for (int ci = 0; ci < CIN; ++ci) {
            #pragma unroll
            for (int ky = 0; ky < 3; ++ky) {
                const int y = h + ky - 1;
                #pragma unroll
                for (int kx = 0; kx < 3; ++kx) {
                    const int x = w + kx - 1;
                    float v = 0.f;
                    if (y >= 0 && y < Hh && x >= 0 && x < Ww)
                        v = __ldg(&inp[ci * HW + y * Ww + x]);
                    acc += v * sw[o * 27 + ci * 9 + ky * 3 + kx];
                }
            }
        }
        spred[gi * GD + o] = acc;
    }
    __syncthreads();

    // ---- phase A2: activation/covariance chain, 1 thread per gaussian ------
    if (tid < 64) {
        const int p = bid * 64 + tid;
        const int w = p % Ww;
        const int h = p / Ww;
        float pred[GD];
        #pragma unroll
        for (int o = 0; o < GD; ++o) pred[o] = spred[tid * GD + o];

        const float theta = (1.f / (1.f + __expf(-pred[3]))) * 6.283185307179586f;
        const float s0 = (1.f / (1.f + __expf(-pred[4]))) * 0.5f + 1e-6f;
        const float s1 = (1.f / (1.f + __expf(-pred[5]))) * 0.5f + 1e-6f;
        const float off0 = tanhf(pred[6]);
        const float off1 = tanhf(pred[7]);

        const float c = __cosf(theta), s = __sinf(theta);
        const float v0 = s0 * s0, v1 = s1 * s1;
        const float S00 = c * c * v0 + s * s * v1;
        const float S01 = c * s * (v0 - v1);
        const float S11 = s * s * v0 + c * c * v1;
        const float det = S00 * S11 - S01 * S01;
        const float inv_det = 1.f / det;

        const float coord0 = 2.0f * (float)w / (float)Ww - 1.0f;
        const float coord1 = 2.0f * (float)h / (float)Hh - 1.0f;
        const float x_ndc = coord0 + 2.0f * off0 / (float)Ww - 1.0f / (float)Ww;
        const float y_ndc = coord1 + 2.0f * off1 / (float)Hh - 1.0f / (float)Hh;

        GParam g;
        g.cx = 0.5f * (float)Ww * (x_ndc + 1.0f) - 0.5f;
        g.cy = 0.5f * (float)Hh * (y_ndc + 1.0f) - 0.5f;
        g.ca =  S11 * inv_det;
        g.cb = -S01 * inv_det;
        g.cc =  S00 * inv_det;
        g.r0 = pred[0]; g.r1 = pred[1]; g.r2 = pred[2];
        g_gauss[p] = g;
    }

    // ---- epoch grid barrier: ONE atomic per block, no reset ----------------
    __threadfence();                     // publish g_gauss GPU-wide
    __syncthreads();                     // whole block done writing
    if (tid == 0) {
        const int my = atomicAdd(&g_arrive, 1);
        const int target = (my / NB + 1) * NB;   // end of this replay's epoch
        while (*(volatile int*)&g_arrive < target) { }
        __threadfence();                 // acquire g_gauss
    }
    __syncthreads();                     // released; all g_gauss visible

    // ---- phase B: rasterize, 8 lanes per pixel, exact 5x5 window -----------
    // cx = w + tanh(off) - 1 in (w-2, w); sigma-gate survivors need
    // |cx - px| <= 1.6645  =>  contributing gaussian cols in [px-1, px+3]
    // (rows symmetric). The removed candidates are provably zero-weight.
    {
        const int gt  = bid * NT + tid;  // [0, 8*HW)
        const int p   = gt >> 3;
        const int sub = gt & 7;
        const int px = p % Ww;
        const int py = p / Ww;
        const float fpx = (float)px;
        const float fpy = (float)py;

        float a0 = 0.f, a1 = 0.f, a2 = 0.f;

        #pragma unroll
        for (int j = sub; j < 25; j += 8) {
            const int gh = py - 1 + j / 5;
            const int gw = px - 1 + j % 5;
            if ((unsigned)gh >= Hh || (unsigned)gw >= Ww) continue;
            const float4* q = reinterpret_cast<const float4*>(&g_gauss[gh * Ww + gw]);
            const float4 q0 = q[0];      // cx, cy, ca, cb
            const float4 q1 = q[1];      // cc, r0, r1, r2
            const float dx = q0.x - fpx;
            const float dy = q0.y - fpy;
            const float sigma = 0.5f * (q0.z * dx * dx + q1.x * dy * dy) + q0.w * dx * dy;
            if (!(sigma >= 0.f) || sigma > LN255) continue;
            const float alpha = fminf(0.999f, __expf(-sigma));
            a0 += alpha * q1.y;
            a1 += alpha * q1.z;
            a2 += alpha * q1.w;
        }

        #pragma unroll
        for (int m = 1; m < 8; m <<= 1) {
            a0 += __shfl_xor_sync(0xFFFFFFFFu, a0, m);
            a1 += __shfl_xor_sync(0xFFFFFFFFu, a1, m);
            a2 += __shfl_xor_sync(0xFFFFFFFFu, a2, m);
        }

        if (sub == 0)      out[0 * HW + p] = fminf(fmaxf(a0, 0.f), 1.f);
        else if (sub == 1) out[1 * HW + p] = fminf(fmaxf(a1, 0.f), 1.f);
        else if (sub == 2) out[2 * HW + p] = fminf(fmaxf(a2, 0.f), 1.f);
    }
}

// ---------------------------------------------------------------------------
extern "C" void kernel_launch(void* const* d_in, const int* in_sizes, int n_in,
                              void* d_out, int out_size)
{
    const float* inp    = (const float*)d_in[0];
    const float* w_enc  = (const float*)d_in[1];
    const float* b_enc  = (const float*)d_in[2];
    const float* w_head = (const float*)d_in[3];
    const float* b_head = (const float*)d_in[4];
    float* out = (float*)d_out;

    fused_kernel<<<NB, NT>>>(inp, w_enc, b_enc, w_head, b_head, out);
}